// round 5
// baseline (speedup 1.0000x reference)
#include <cuda_runtime.h>
#include <cuda_bf16.h>

// S=4096, H=3, E=512, G=3334, F=1, res=0.03
// out = sum_{s,h,e} mask*(b_h + w_h*feat)  -  0.03 * sum_{s,h,g} exp(b_h + w_h*grid)
//
// Row-aligned scheme: R = S*H = 12288 rows. 4096 warps; warp w owns rows
// 3w+0, 3w+1, 3w+2 which have h = 0,1,2 exactly -> h is a compile-time literal.

#define S_DIM 4096
#define H_DIM 3
#define E_DIM 512
#define G_DIM 3334

constexpr int NBLK = 512;
constexpr int NTHR = 256;
constexpr int NWARP = NBLK * (NTHR / 32);     // 4096
constexpr int ROWS = S_DIM * H_DIM;           // 12288 = 3 * NWARP

constexpr int EV_ROW4 = E_DIM / 4;            // 128 float4 per event row
constexpr int GR_ROW2 = G_DIM / 2;            // 1667 float2 per grid row
constexpr int GR_FULL = (GR_ROW2 / 32) * 32;  // 1664

__device__ float g_part_log[NBLK];
__device__ float g_part_int[NBLK];
__device__ unsigned int g_done_count = 0;

__global__ void __launch_bounds__(NTHR, 8) lm_fused_kernel(
    const float* __restrict__ ev_feat,
    const int* __restrict__ ev_mask,      // bool -> int32 in the harness
    const float* __restrict__ gr_feat,
    const float* __restrict__ weights,
    const float* __restrict__ bases,
    const float* __restrict__ effects,
    float* __restrict__ out)
{
    const int lane = threadIdx.x & 31;
    const int wid  = threadIdx.x >> 5;
    const int warp = blockIdx.x * (NTHR / 32) + wid;   // 0..4095

    // Per-head constants
    float wv[3], bv[3], wl[3], bl[3];
    #pragma unroll
    for (int h = 0; h < 3; h++) {
        wv[h] = weights[h] * effects[h];
        bv[h] = bases[h];
        wl[h] = wv[h] * 1.4426950408889634f;   // fold log2(e) for exp2
        bl[h] = bv[h] * 1.4426950408889634f;
    }

    float plog = 0.0f;
    float pint = 0.0f;

    // ---- Event part: rows 3*warp + h, h = 0,1,2 ----
    {
        #pragma unroll
        for (int h = 0; h < 3; h++) {
            const int row = 3 * warp + h;
            const float4* __restrict__ f4 = (const float4*)ev_feat + (size_t)row * EV_ROW4;
            const int4*   __restrict__ m4 = (const int4*)ev_mask + (size_t)row * EV_ROW4;
            int   cnt = 0;
            float sum = 0.0f;
            #pragma unroll
            for (int i = 0; i < 4; i++) {
                const int k = lane + 32 * i;
                const float4 f = f4[k];
                const int4   m = m4[k];
                if (m.x) { cnt++; sum += f.x; }
                if (m.y) { cnt++; sum += f.y; }
                if (m.z) { cnt++; sum += f.z; }
                if (m.w) { cnt++; sum += f.w; }
            }
            plog += fmaf(bv[h], (float)cnt, wv[h] * sum);
        }
    }

    // ---- Grid part: rows 3*warp + h ----
    {
        #pragma unroll
        for (int h = 0; h < 3; h++) {
            const int row = 3 * warp + h;
            const float2* __restrict__ g2 = (const float2*)gr_feat + (size_t)row * GR_ROW2;
            const float ww = wl[h];
            const float bb = bl[h];
            float acc = 0.0f;
            int k = lane;
            #pragma unroll 4
            for (; k < GR_FULL; k += 32) {
                const float2 g = g2[k];
                acc += exp2f(fmaf(ww, g.x, bb));
                acc += exp2f(fmaf(ww, g.y, bb));
            }
            if (k < GR_ROW2) {                 // lanes 0..2 handle the 3-element tail
                const float2 g = g2[k];
                acc += exp2f(fmaf(ww, g.x, bb));
                acc += exp2f(fmaf(ww, g.y, bb));
            }
            pint += acc;
        }
    }

    // ---- Block reduction ----
    __shared__ float s_log[NTHR / 32];
    __shared__ float s_int[NTHR / 32];
    __shared__ bool s_is_last;
    #pragma unroll
    for (int off = 16; off > 0; off >>= 1) {
        plog += __shfl_xor_sync(0xFFFFFFFFu, plog, off);
        pint += __shfl_xor_sync(0xFFFFFFFFu, pint, off);
    }
    if (lane == 0) { s_log[wid] = plog; s_int[wid] = pint; }
    __syncthreads();
    if (wid == 0) {
        float vl = (lane < NTHR / 32) ? s_log[lane] : 0.0f;
        float vi = (lane < NTHR / 32) ? s_int[lane] : 0.0f;
        #pragma unroll
        for (int off = 4; off > 0; off >>= 1) {
            vl += __shfl_xor_sync(0xFFFFFFFFu, vl, off);
            vi += __shfl_xor_sync(0xFFFFFFFFu, vi, off);
        }
        if (lane == 0) {
            g_part_log[blockIdx.x] = vl;
            g_part_int[blockIdx.x] = vi;
            __threadfence();
            unsigned int ticket = atomicAdd(&g_done_count, 1u);
            s_is_last = (ticket == (unsigned int)(NBLK - 1));
        }
    }
    __syncthreads();

    // ---- Last block: deterministic final combine in double ----
    if (s_is_last) {
        __shared__ double d_log[NTHR / 32];
        __shared__ double d_int[NTHR / 32];
        double dl = 0.0, di = 0.0;
        for (int j = threadIdx.x; j < NBLK; j += NTHR) {
            dl += (double)g_part_log[j];
            di += (double)g_part_int[j];
        }
        #pragma unroll
        for (int off = 16; off > 0; off >>= 1) {
            dl += __shfl_xor_sync(0xFFFFFFFFu, dl, off);
            di += __shfl_xor_sync(0xFFFFFFFFu, di, off);
        }
        if (lane == 0) { d_log[wid] = dl; d_int[wid] = di; }
        __syncthreads();
        if (threadIdx.x == 0) {
            double tl = 0.0, ti = 0.0;
            #pragma unroll
            for (int k = 0; k < NTHR / 32; k++) { tl += d_log[k]; ti += d_int[k]; }
            out[0] = (float)(tl - 0.03 * ti);
            g_done_count = 0;   // reset for next graph replay
        }
    }
}

extern "C" void kernel_launch(void* const* d_in, const int* in_sizes, int n_in,
                              void* d_out, int out_size)
{
    const float* ev_feat = (const float*)d_in[0];
    const int*   ev_mask = (const int*)d_in[1];
    const float* gr_feat = (const float*)d_in[2];
    const float* weights = (const float*)d_in[3];
    const float* bases   = (const float*)d_in[4];
    const float* effects = (const float*)d_in[5];
    float* out = (float*)d_out;

    lm_fused_kernel<<<NBLK, NTHR>>>(ev_feat, ev_mask, gr_feat, weights, bases, effects, out);
}

// round 7
// speedup vs baseline: 1.1000x; 1.1000x over previous
#include <cuda_runtime.h>
#include <cuda_bf16.h>

// S=4096, H=3, E=512, G=3334, F=1, res=0.03
// out = sum_{s,h,e} mask*(b_h + w_h*feat)  -  0.03 * sum_{s,h,g} exp(b_h + w_h*grid)
//
// Row-aligned + row-halved: 12288 rows = 3 * 4096 pairs. 8192 warps; warp w
// -> pair p = w>>1 (rows 3p+0/1/2, h literal), half = w&1 (first/second half
// of each row). Restores ~85% occupancy while keeping zero div/mod indexing.

#define S_DIM 4096
#define H_DIM 3
#define E_DIM 512
#define G_DIM 3334

constexpr int NBLK = 1024;
constexpr int NTHR = 256;

constexpr int EV_ROW4 = E_DIM / 4;            // 128 float4 per event row
constexpr int GR_ROW2 = G_DIM / 2;            // 1667 float2 per grid row
constexpr int GR_HALF_ITERS = 26;             // 26*32 = 832 float2 per half
constexpr int GR_SPLIT = 832;                 // half1 covers [832, 1667)

__device__ float g_part_log[NBLK];
__device__ float g_part_int[NBLK];
__device__ unsigned int g_done_count = 0;

__global__ void __launch_bounds__(NTHR, 8) lm_fused_kernel(
    const float* __restrict__ ev_feat,
    const int* __restrict__ ev_mask,      // bool -> int32 in the harness
    const float* __restrict__ gr_feat,
    const float* __restrict__ weights,
    const float* __restrict__ bases,
    const float* __restrict__ effects,
    float* __restrict__ out)
{
    const int lane = threadIdx.x & 31;
    const int wid  = threadIdx.x >> 5;
    const int warp = blockIdx.x * (NTHR / 32) + wid;   // 0..8191
    const int pair = warp >> 1;                        // 0..4095
    const int half = warp & 1;                         // 0 or 1

    // Per-head constants
    float wv[3], bv[3], wl[3], bl[3];
    #pragma unroll
    for (int h = 0; h < 3; h++) {
        wv[h] = weights[h] * effects[h];
        bv[h] = bases[h];
        wl[h] = wv[h] * 1.4426950408889634f;   // fold log2(e) for exp2
        bl[h] = bv[h] * 1.4426950408889634f;
    }

    float plog = 0.0f;
    float pint = 0.0f;

    // ---- Event part: rows 3*pair + h, this warp's half (64 float4) ----
    {
        const int kbase = half * (EV_ROW4 / 2) + lane;   // 0/64 + lane
        #pragma unroll
        for (int h = 0; h < 3; h++) {
            const int row = 3 * pair + h;
            const float4* __restrict__ f4 = (const float4*)ev_feat + (size_t)row * EV_ROW4;
            const int4*   __restrict__ m4 = (const int4*)ev_mask + (size_t)row * EV_ROW4;
            int   cnt = 0;
            float sum = 0.0f;
            #pragma unroll
            for (int i = 0; i < 2; i++) {
                const int k = kbase + 32 * i;
                const float4 f = f4[k];
                const int4   m = m4[k];
                if (m.x) { cnt++; sum += f.x; }
                if (m.y) { cnt++; sum += f.y; }
                if (m.z) { cnt++; sum += f.z; }
                if (m.w) { cnt++; sum += f.w; }
            }
            plog += fmaf(bv[h], (float)cnt, wv[h] * sum);
        }
    }

    // ---- Grid part: rows 3*pair + h, this warp's half ----
    {
        const int kbase = half * GR_SPLIT + lane;
        #pragma unroll
        for (int h = 0; h < 3; h++) {
            const int row = 3 * pair + h;
            const float2* __restrict__ g2 = (const float2*)gr_feat + (size_t)row * GR_ROW2;
            const float ww = wl[h];
            const float bb = bl[h];
            float acc = 0.0f;
            #pragma unroll 4
            for (int i = 0; i < GR_HALF_ITERS; i++) {
                const float2 g = g2[kbase + 32 * i];
                acc += exp2f(fmaf(ww, g.x, bb));
                acc += exp2f(fmaf(ww, g.y, bb));
            }
            if (half == 1 && lane < GR_ROW2 - 2 * GR_SPLIT) {   // tail: 1664..1666 (3 float2)
                const float2 g = g2[2 * GR_SPLIT + lane];
                acc += exp2f(fmaf(ww, g.x, bb));
                acc += exp2f(fmaf(ww, g.y, bb));
            }
            pint += acc;
        }
    }

    // ---- Block reduction ----
    __shared__ float s_log[NTHR / 32];
    __shared__ float s_int[NTHR / 32];
    __shared__ bool s_is_last;
    #pragma unroll
    for (int off = 16; off > 0; off >>= 1) {
        plog += __shfl_xor_sync(0xFFFFFFFFu, plog, off);
        pint += __shfl_xor_sync(0xFFFFFFFFu, pint, off);
    }
    if (lane == 0) { s_log[wid] = plog; s_int[wid] = pint; }
    __syncthreads();
    if (wid == 0) {
        float vl = (lane < NTHR / 32) ? s_log[lane] : 0.0f;
        float vi = (lane < NTHR / 32) ? s_int[lane] : 0.0f;
        #pragma unroll
        for (int off = 4; off > 0; off >>= 1) {
            vl += __shfl_xor_sync(0xFFFFFFFFu, vl, off);
            vi += __shfl_xor_sync(0xFFFFFFFFu, vi, off);
        }
        if (lane == 0) {
            g_part_log[blockIdx.x] = vl;
            g_part_int[blockIdx.x] = vi;
            __threadfence();
            unsigned int ticket = atomicAdd(&g_done_count, 1u);
            s_is_last = (ticket == (unsigned int)(NBLK - 1));
        }
    }
    __syncthreads();

    // ---- Last block: deterministic final combine in double ----
    if (s_is_last) {
        __shared__ double d_log[NTHR / 32];
        __shared__ double d_int[NTHR / 32];
        double dl = 0.0, di = 0.0;
        for (int j = threadIdx.x; j < NBLK; j += NTHR) {
            dl += (double)g_part_log[j];
            di += (double)g_part_int[j];
        }
        #pragma unroll
        for (int off = 16; off > 0; off >>= 1) {
            dl += __shfl_xor_sync(0xFFFFFFFFu, dl, off);
            di += __shfl_xor_sync(0xFFFFFFFFu, di, off);
        }
        if (lane == 0) { d_log[wid] = dl; d_int[wid] = di; }
        __syncthreads();
        if (threadIdx.x == 0) {
            double tl = 0.0, ti = 0.0;
            #pragma unroll
            for (int k = 0; k < NTHR / 32; k++) { tl += d_log[k]; ti += d_int[k]; }
            out[0] = (float)(tl - 0.03 * ti);
            g_done_count = 0;   // reset for next graph replay
        }
    }
}

extern "C" void kernel_launch(void* const* d_in, const int* in_sizes, int n_in,
                              void* d_out, int out_size)
{
    const float* ev_feat = (const float*)d_in[0];
    const int*   ev_mask = (const int*)d_in[1];
    const float* gr_feat = (const float*)d_in[2];
    const float* weights = (const float*)d_in[3];
    const float* bases   = (const float*)d_in[4];
    const float* effects = (const float*)d_in[5];
    float* out = (float*)d_out;

    lm_fused_kernel<<<NBLK, NTHR>>>(ev_feat, ev_mask, gr_feat, weights, bases, effects, out);
}